// round 4
// baseline (speedup 1.0000x reference)
#include <cuda_runtime.h>
#include <cstdint>
#include <math.h>

#define BATCH 4
#define SEQ 2048
#define DIM 512
#define NH 8
#define HD 64
#define INNER 512
#define MTOT (BATCH*SEQ)
#define NQKV (3*INNER)
#define EXP_C 0.18033688f   // 0.125 * log2(e)

// ---- scratch (__device__ globals; alloc-free rule) ----
__device__ float g_q[(size_t)BATCH*NH*SEQ*HD];
__device__ float g_k[(size_t)BATCH*NH*SEQ*HD];
__device__ float g_v[(size_t)BATCH*NH*SEQ*HD];
__device__ float g_o[(size_t)MTOT*INNER];
__device__ float g_xr[(size_t)MTOT*DIM];
__device__ float g_wqkvT[(size_t)NQKV*DIM];
__device__ float g_woutT[(size_t)DIM*INNER];

// =============== helpers ===============
__device__ __forceinline__ uint32_t smem_u32(const void* p){
    uint32_t a;
    asm("{ .reg .u64 t; cvta.to.shared.u64 t, %1; cvt.u32.u64 %0, t; }":"=r"(a):"l"(p));
    return a;
}
__device__ __forceinline__ float to_tf32(float x){
    uint32_t r; asm("cvt.rna.tf32.f32 %0, %1;" : "=r"(r) : "f"(x));
    return __uint_as_float(r);
}
__device__ __forceinline__ float ex2f(float x){
    float r; asm("ex2.approx.f32 %0, %1;" : "=f"(r) : "f"(x)); return r;
}
#define CP16(dst,src) asm volatile("cp.async.cg.shared.global [%0], [%1], 16;" :: "r"(dst), "l"(src) : "memory")
#define CP_COMMIT()   asm volatile("cp.async.commit_group;" ::: "memory")
#define CP_WAIT0()    asm volatile("cp.async.wait_group 0;" ::: "memory")
#define CP_WAIT1()    asm volatile("cp.async.wait_group 1;" ::: "memory")

__device__ __forceinline__ void mma_tf32(float c[4], const uint32_t a[4], const uint32_t b[2]){
    asm volatile("mma.sync.aligned.m16n8k8.row.col.f32.tf32.tf32.f32 "
        "{%0,%1,%2,%3},{%4,%5,%6,%7},{%8,%9},{%0,%1,%2,%3};"
        : "+f"(c[0]),"+f"(c[1]),"+f"(c[2]),"+f"(c[3])
        : "r"(a[0]),"r"(a[1]),"r"(a[2]),"r"(a[3]),"r"(b[0]),"r"(b[1]));
}

// =============== pre-pass kernels ===============
__global__ void round_x(const float4* __restrict__ src, float4* __restrict__ dst){
    int i = blockIdx.x * blockDim.x + threadIdx.x;
    float4 v = src[i];
    v.x = to_tf32(v.x); v.y = to_tf32(v.y); v.z = to_tf32(v.z); v.w = to_tf32(v.w);
    dst[i] = v;
}

__global__ void transpose_mat(const float* __restrict__ src, float* __restrict__ dst,
                              int R, int C){
    __shared__ float t[32][33];
    int bx = blockIdx.x * 32, by = blockIdx.y * 32;
    int tx = threadIdx.x;
    for (int yy = threadIdx.y; yy < 32; yy += 8)
        t[yy][tx] = src[(size_t)(by+yy)*C + bx + tx];
    __syncthreads();
    for (int yy = threadIdx.y; yy < 32; yy += 8)
        dst[(size_t)(bx+yy)*R + by + tx] = to_tf32(t[tx][yy]);
}

// =============== shared GEMM mainloop (triple-buffered) ===============
#define GEMM_BUF 4608
#define GEMM_SMEM (6*GEMM_BUF*4)   // 110592 B

__device__ __forceinline__ void tile_gemm(const float* __restrict__ Ag,
                                          const float* __restrict__ Bg,
                                          float acc[4][4][4], float* sm, int tid){
    const int f = tid & 7, r0 = tid >> 3;
    const int lane = tid & 31, wid = tid >> 5;
    const int g = lane >> 2, tig = lane & 3;
    const int wm = wid >> 2, wn = wid & 3;
    float* As = sm;
    float* Bs = sm + 3*GEMM_BUF;
    uint32_t asb = smem_u32(As), bsb = smem_u32(Bs);

    // prologue: chunks 0,1
#pragma unroll
    for (int c = 0; c < 2; c++){
#pragma unroll
        for (int i = 0; i < 4; i++){
            int r = r0 + i*32;
            CP16(asb + (c*GEMM_BUF + r*36 + f*4)*4, Ag + (size_t)r*512 + c*32 + f*4);
            CP16(bsb + (c*GEMM_BUF + r*36 + f*4)*4, Bg + (size_t)r*512 + c*32 + f*4);
        }
        CP_COMMIT();
    }

    for (int kc = 0; kc < 16; kc++){
        if (kc == 15) CP_WAIT0(); else CP_WAIT1();
        __syncthreads();
        if (kc + 2 < 16){
            int k0 = (kc+2)*32, nb = (kc+2)%3;
#pragma unroll
            for (int i = 0; i < 4; i++){
                int r = r0 + i*32;
                CP16(asb + (nb*GEMM_BUF + r*36 + f*4)*4, Ag + (size_t)r*512 + k0 + f*4);
                CP16(bsb + (nb*GEMM_BUF + r*36 + f*4)*4, Bg + (size_t)r*512 + k0 + f*4);
            }
            CP_COMMIT();
        }
        const float* Ab = As + (kc%3)*GEMM_BUF;
        const float* Bb = Bs + (kc%3)*GEMM_BUF;
#pragma unroll
        for (int ks = 0; ks < 4; ks++){
            uint32_t a[4][4], b[4][2];
#pragma unroll
            for (int mf = 0; mf < 4; mf++){
                int row = wm*64 + mf*16 + g;
                const uint32_t* p0 = (const uint32_t*)(Ab + row*36 + ks*8);
                const uint32_t* p1 = (const uint32_t*)(Ab + (row+8)*36 + ks*8);
                a[mf][0] = p0[tig];   a[mf][1] = p1[tig];
                a[mf][2] = p0[tig+4]; a[mf][3] = p1[tig+4];
            }
#pragma unroll
            for (int nf = 0; nf < 4; nf++){
                int n = wn*32 + nf*8 + g;
                const uint32_t* p = (const uint32_t*)(Bb + n*36 + ks*8);
                b[nf][0] = p[tig]; b[nf][1] = p[tig+4];
            }
#pragma unroll
            for (int mf = 0; mf < 4; mf++)
#pragma unroll
                for (int nf = 0; nf < 4; nf++)
                    mma_tf32(acc[mf][nf], a[mf], b[nf]);
        }
    }
}

// =============== QKV GEMM ===============
__global__ __launch_bounds__(256,2) void gemm_qkv(){
    extern __shared__ float sm[];
    int tid = threadIdx.x;
    int c0 = blockIdx.x*128, m0 = blockIdx.y*128;
    float acc[4][4][4] = {};
    tile_gemm(g_xr + (size_t)m0*512, g_wqkvT + (size_t)c0*512, acc, sm, tid);

    const int lane = tid & 31, wid = tid >> 5;
    const int g = lane >> 2, tig = lane & 3;
    const int wm = wid >> 2, wn = wid & 3;
    int sec = c0 >> 9;
    float* dstBase = (sec == 0) ? g_q : (sec == 1 ? g_k : g_v);
    int s0 = (c0 & 511) + wn*32;
    int bb = (m0 >> 11);
#pragma unroll
    for (int mf = 0; mf < 4; mf++){
        int r = m0 + wm*64 + mf*16 + g;
        int n = r & 2047;
#pragma unroll
        for (int nf = 0; nf < 4; nf++){
            int s = s0 + nf*8 + 2*tig;
            int h = s >> 6, d = s & 63;
            float* p = dstBase + ((size_t)((bb*NH + h)*SEQ + n))*HD + d;
            float2 v0 = make_float2(to_tf32(acc[mf][nf][0]), to_tf32(acc[mf][nf][1]));
            float2 v1 = make_float2(to_tf32(acc[mf][nf][2]), to_tf32(acc[mf][nf][3]));
            *reinterpret_cast<float2*>(p) = v0;
            *reinterpret_cast<float2*>(p + 8*HD) = v1;
        }
    }
}

// =============== Out GEMM + bias ===============
__global__ __launch_bounds__(256,2) void gemm_out(const float* __restrict__ bias,
                                                  float* __restrict__ out){
    extern __shared__ float sm[];
    int tid = threadIdx.x;
    int c0 = blockIdx.x*128, m0 = blockIdx.y*128;
    float acc[4][4][4] = {};
    tile_gemm(g_o + (size_t)m0*512, g_woutT + (size_t)c0*512, acc, sm, tid);

    const int lane = tid & 31, wid = tid >> 5;
    const int g = lane >> 2, tig = lane & 3;
    const int wm = wid >> 2, wn = wid & 3;
#pragma unroll
    for (int mf = 0; mf < 4; mf++){
        int r = m0 + wm*64 + mf*16 + g;
#pragma unroll
        for (int nf = 0; nf < 4; nf++){
            int c = c0 + wn*32 + nf*8 + 2*tig;
            float2 bv = *reinterpret_cast<const float2*>(bias + c);
            float2 v0 = make_float2(acc[mf][nf][0] + bv.x, acc[mf][nf][1] + bv.y);
            float2 v1 = make_float2(acc[mf][nf][2] + bv.x, acc[mf][nf][3] + bv.y);
            *reinterpret_cast<float2*>(out + (size_t)r*DIM + c) = v0;
            *reinterpret_cast<float2*>(out + (size_t)(r+8)*DIM + c) = v1;
        }
    }
}

// =============== Flash attention (512 threads, 16 warps) ===============
// smem floats: Q[128*68], K[128*68], V[2][128*68], P[128*132], l[128]
#define FQ 0
#define FK 8704
#define FV 17408
#define FP 34816
#define FL 51712
#define FLASH_SMEM (51840*4)

__global__ __launch_bounds__(512,1) void flash_tc(){
    extern __shared__ float sm[];
    const int tid = threadIdx.x;
    const int lane = tid & 31, wid = tid >> 5;
    const int g = lane >> 2, tig = lane & 3;
    const int wq = wid >> 2, wc = wid & 3;     // 4x4 warp grid
    const int q0 = blockIdx.x*128, h = blockIdx.y, b = blockIdx.z;

    const float* Qg = g_q + ((size_t)(b*NH+h)*SEQ + q0)*HD;
    const float* Kg = g_k + (size_t)(b*NH+h)*SEQ*HD;
    const float* Vg = g_v + (size_t)(b*NH+h)*SEQ*HD;

    float* Qs = sm + FQ;
    float* Ks = sm + FK;
    float* Ps = sm + FP;
    float* l_sm = sm + FL;
    uint32_t sb = smem_u32(sm);

    if (tid < 128) l_sm[tid] = 0.f;

    // prologue: Q, K0, V0
    {
        const int f = tid & 15, r0 = tid >> 4;   // r0: 0..31
#pragma unroll
        for (int i = 0; i < 4; i++){
            int r = r0 + i*32;
            CP16(sb + (FQ + r*68 + f*4)*4, Qg + (size_t)r*HD + f*4);
            CP16(sb + (FK + r*68 + f*4)*4, Kg + (size_t)r*HD + f*4);
            CP16(sb + (FV + r*68 + f*4)*4, Vg + (size_t)r*HD + f*4);
        }
        CP_COMMIT();
    }

    float oacc[2][2][4] = {};

    for (int t = 0; t < 16; t++){
        CP_WAIT0();
        __syncthreads();
        const float* Vb = sm + FV + (t&1)*8704;

        // ---- S = Q @ K^T : warp tile 32x32 ----
        float sacc[2][4][4] = {};
#pragma unroll
        for (int ks = 0; ks < 8; ks++){
            uint32_t a[2][4], bq[4][2];
#pragma unroll
            for (int mf = 0; mf < 2; mf++){
                int row = wq*32 + mf*16 + g;
                const uint32_t* p0 = (const uint32_t*)(Qs + row*68 + ks*8);
                const uint32_t* p1 = (const uint32_t*)(Qs + (row+8)*68 + ks*8);
                a[mf][0] = p0[tig];   a[mf][1] = p1[tig];
                a[mf][2] = p0[tig+4]; a[mf][3] = p1[tig+4];
            }
#pragma unroll
            for (int nf = 0; nf < 4; nf++){
                int n = wc*32 + nf*8 + g;
                const uint32_t* p = (const uint32_t*)(Ks + n*68 + ks*8);
                bq[nf][0] = p[tig]; bq[nf][1] = p[tig+4];
            }
#pragma unroll
            for (int mf = 0; mf < 2; mf++)
#pragma unroll
                for (int nf = 0; nf < 4; nf++)
                    mma_tf32(sacc[mf][nf], a[mf], bq[nf]);
        }

        // ---- softmax (no max subtraction), write P ----
#pragma unroll
        for (int mf = 0; mf < 2; mf++){
            int row = wq*32 + mf*16 + g;
            float s0 = 0.f, s1 = 0.f;
#pragma unroll
            for (int nf = 0; nf < 4; nf++){
                float p0 = to_tf32(ex2f(sacc[mf][nf][0]*EXP_C));
                float p1 = to_tf32(ex2f(sacc[mf][nf][1]*EXP_C));
                float p2 = to_tf32(ex2f(sacc[mf][nf][2]*EXP_C));
                float p3 = to_tf32(ex2f(sacc[mf][nf][3]*EXP_C));
                s0 += p0 + p1; s1 += p2 + p3;
                int col = wc*32 + nf*8 + 2*tig;
                *reinterpret_cast<float2*>(Ps + row*132 + col)     = make_float2(p0, p1);
                *reinterpret_cast<float2*>(Ps + (row+8)*132 + col) = make_float2(p2, p3);
            }
            s0 += __shfl_xor_sync(0xffffffffu, s0, 1);
            s0 += __shfl_xor_sync(0xffffffffu, s0, 2);
            s1 += __shfl_xor_sync(0xffffffffu, s1, 1);
            s1 += __shfl_xor_sync(0xffffffffu, s1, 2);
            if (tig == 0){
                atomicAdd(l_sm + row, s0);
                atomicAdd(l_sm + row + 8, s1);
            }
        }
        __syncthreads();   // P complete; K free for overwrite

        // prefetch next K, V
        if (t < 15){
            const int f = tid & 15, r0 = tid >> 4;
            const float* Kn = Kg + (size_t)(t+1)*128*HD;
            const float* Vn = Vg + (size_t)(t+1)*128*HD;
            uint32_t voff = FV + ((t+1)&1)*8704;
#pragma unroll
            for (int i = 0; i < 4; i++){
                int r = r0 + i*32;
                CP16(sb + (FK + r*68 + f*4)*4, Kn + (size_t)r*HD + f*4);
                CP16(sb + (voff + r*68 + f*4)*4, Vn + (size_t)r*HD + f*4);
            }
            CP_COMMIT();
        }

        // ---- O += P @ V : warp tile 32x16 ----
#pragma unroll 4
        for (int ks = 0; ks < 16; ks++){
            uint32_t a[2][4], bv[2][2];
#pragma unroll
            for (int mf = 0; mf < 2; mf++){
                int row = wq*32 + mf*16 + g;
                const uint32_t* p0 = (const uint32_t*)(Ps + row*132 + ks*8);
                const uint32_t* p1 = (const uint32_t*)(Ps + (row+8)*132 + ks*8);
                a[mf][0] = p0[tig];   a[mf][1] = p1[tig];
                a[mf][2] = p0[tig+4]; a[mf][3] = p1[tig+4];
            }
#pragma unroll
            for (int nf = 0; nf < 2; nf++){
                int c = wc*16 + nf*8 + g;
                bv[nf][0] = *(const uint32_t*)(Vb + (ks*8 + tig)*68 + c);
                bv[nf][1] = *(const uint32_t*)(Vb + (ks*8 + tig + 4)*68 + c);
            }
#pragma unroll
            for (int mf = 0; mf < 2; mf++)
#pragma unroll
                for (int nf = 0; nf < 2; nf++)
                    mma_tf32(oacc[mf][nf], a[mf], bv[nf]);
        }
    }

    __syncthreads();
    // epilogue: normalize, round, write [b,n,h*64+d]
#pragma unroll
    for (int mf = 0; mf < 2; mf++){
        int row = wq*32 + mf*16 + g;
        float inv0 = 1.f / l_sm[row];
        float inv1 = 1.f / l_sm[row + 8];
        int n = q0 + row;
        float* base0 = g_o + ((size_t)(b*SEQ + n))*INNER + h*HD;
        float* base1 = base0 + (size_t)8*INNER;
#pragma unroll
        for (int nf = 0; nf < 2; nf++){
            int d = wc*16 + nf*8 + 2*tig;
            *reinterpret_cast<float2*>(base0 + d) =
                make_float2(to_tf32(oacc[mf][nf][0]*inv0), to_tf32(oacc[mf][nf][1]*inv0));
            *reinterpret_cast<float2*>(base1 + d) =
                make_float2(to_tf32(oacc[mf][nf][2]*inv1), to_tf32(oacc[mf][nf][3]*inv1));
        }
    }
}

// =============== launch ===============
extern "C" void kernel_launch(void* const* d_in, const int* in_sizes, int n_in,
                              void* d_out, int out_size) {
    const float* x     = (const float*)d_in[0];
    const float* w_qkv = (const float*)d_in[1];
    const float* w_out = (const float*)d_in[2];
    const float* b_out = (const float*)d_in[3];
    float* out = (float*)d_out;

    cudaFuncSetAttribute(gemm_qkv, cudaFuncAttributeMaxDynamicSharedMemorySize, GEMM_SMEM);
    cudaFuncSetAttribute(gemm_out, cudaFuncAttributeMaxDynamicSharedMemorySize, GEMM_SMEM);
    cudaFuncSetAttribute(flash_tc, cudaFuncAttributeMaxDynamicSharedMemorySize, FLASH_SMEM);

    float4* xr4;
    { void* p; cudaGetSymbolAddress(&p, g_xr); xr4 = (float4*)p; }
    float* wqkvT; { void* p; cudaGetSymbolAddress(&p, g_wqkvT); wqkvT = (float*)p; }
    float* woutT; { void* p; cudaGetSymbolAddress(&p, g_woutT); woutT = (float*)p; }

    round_x<<<(MTOT*DIM/4)/512, 512>>>((const float4*)x, xr4);
    transpose_mat<<<dim3(NQKV/32, DIM/32), dim3(32,8)>>>(w_qkv, wqkvT, DIM, NQKV);
    transpose_mat<<<dim3(DIM/32, INNER/32), dim3(32,8)>>>(w_out, woutT, INNER, DIM);

    gemm_qkv<<<dim3(NQKV/128, MTOT/128), 256, GEMM_SMEM>>>();
    flash_tc<<<dim3(SEQ/128, NH, BATCH), 512, FLASH_SMEM>>>();
    gemm_out<<<dim3(DIM/128, MTOT/128), 256, GEMM_SMEM>>>(b_out, out);
}

// round 5
// speedup vs baseline: 1.7217x; 1.7217x over previous
#include <cuda_runtime.h>
#include <cstdint>
#include <math.h>

#define BATCH 4
#define SEQ 2048
#define DIM 512
#define NH 8
#define HD 64
#define INNER 512
#define MTOT (BATCH*SEQ)
#define NQKV (3*INNER)
#define EXP_C 0.18033688f   // 0.125 * log2(e)

// ---- scratch (__device__ globals; alloc-free rule) ----
__device__ float g_q[(size_t)BATCH*NH*SEQ*HD];
__device__ float g_k[(size_t)BATCH*NH*SEQ*HD];
__device__ float g_v[(size_t)BATCH*NH*SEQ*HD];
__device__ float g_o[(size_t)MTOT*INNER];
__device__ float g_xr[(size_t)MTOT*DIM];
__device__ float g_wqkvT[(size_t)NQKV*DIM];
__device__ float g_woutT[(size_t)DIM*INNER];

// =============== helpers ===============
__device__ __forceinline__ uint32_t smem_u32(const void* p){
    uint32_t a;
    asm("{ .reg .u64 t; cvta.to.shared.u64 t, %1; cvt.u32.u64 %0, t; }":"=r"(a):"l"(p));
    return a;
}
__device__ __forceinline__ float to_tf32(float x){
    uint32_t r; asm("cvt.rna.tf32.f32 %0, %1;" : "=r"(r) : "f"(x));
    return __uint_as_float(r);
}
__device__ __forceinline__ float ex2f(float x){
    float r; asm("ex2.approx.f32 %0, %1;" : "=f"(r) : "f"(x)); return r;
}
#define CP16(dst,src) asm volatile("cp.async.cg.shared.global [%0], [%1], 16;" :: "r"(dst), "l"(src) : "memory")
#define CP_COMMIT()   asm volatile("cp.async.commit_group;" ::: "memory")
#define CP_WAIT0()    asm volatile("cp.async.wait_group 0;" ::: "memory")

__device__ __forceinline__ void mma_tf32(float c[4], const uint32_t a[4], const uint32_t b[2]){
    asm volatile("mma.sync.aligned.m16n8k8.row.col.f32.tf32.tf32.f32 "
        "{%0,%1,%2,%3},{%4,%5,%6,%7},{%8,%9},{%0,%1,%2,%3};"
        : "+f"(c[0]),"+f"(c[1]),"+f"(c[2]),"+f"(c[3])
        : "r"(a[0]),"r"(a[1]),"r"(a[2]),"r"(a[3]),"r"(b[0]),"r"(b[1]));
}

// =============== pre-pass kernels ===============
__global__ void round_x(const float4* __restrict__ src, float4* __restrict__ dst){
    int i = blockIdx.x * blockDim.x + threadIdx.x;
    float4 v = src[i];
    v.x = to_tf32(v.x); v.y = to_tf32(v.y); v.z = to_tf32(v.z); v.w = to_tf32(v.w);
    dst[i] = v;
}

__global__ void transpose_mat(const float* __restrict__ src, float* __restrict__ dst,
                              int R, int C){
    __shared__ float t[32][33];
    int bx = blockIdx.x * 32, by = blockIdx.y * 32;
    int tx = threadIdx.x;
    for (int yy = threadIdx.y; yy < 32; yy += 8)
        t[yy][tx] = src[(size_t)(by+yy)*C + bx + tx];
    __syncthreads();
    for (int yy = threadIdx.y; yy < 32; yy += 8)
        dst[(size_t)(bx+yy)*R + by + tx] = to_tf32(t[tx][yy]);
}

// =============== shared GEMM mainloop (R3 double-buffered) ===============
#define GEMM_BUF 4608
#define GEMM_SMEM (4*GEMM_BUF*4)

__device__ __forceinline__ void tile_gemm(const float* __restrict__ Ag,
                                          const float* __restrict__ Bg,
                                          float acc[4][4][4], float* sm, int tid){
    const int f = tid & 7, r0 = tid >> 3;
    const int lane = tid & 31, wid = tid >> 5;
    const int g = lane >> 2, tig = lane & 3;
    const int wm = wid >> 2, wn = wid & 3;
    float* As = sm;
    float* Bs = sm + 2*GEMM_BUF;
    uint32_t asb = smem_u32(As), bsb = smem_u32(Bs);

#pragma unroll
    for (int i = 0; i < 4; i++){
        int r = r0 + i*32;
        CP16(asb + (r*36 + f*4)*4, Ag + (size_t)r*512 + f*4);
        CP16(bsb + (r*36 + f*4)*4, Bg + (size_t)r*512 + f*4);
    }
    CP_COMMIT();

    int buf = 0;
    for (int kc = 0; kc < 16; kc++){
        CP_WAIT0();
        __syncthreads();
        if (kc < 15){
            int k0 = (kc+1)*32, nb = buf ^ 1;
#pragma unroll
            for (int i = 0; i < 4; i++){
                int r = r0 + i*32;
                CP16(asb + (nb*GEMM_BUF + r*36 + f*4)*4, Ag + (size_t)r*512 + k0 + f*4);
                CP16(bsb + (nb*GEMM_BUF + r*36 + f*4)*4, Bg + (size_t)r*512 + k0 + f*4);
            }
            CP_COMMIT();
        }
        const float* Ab = As + buf*GEMM_BUF;
        const float* Bb = Bs + buf*GEMM_BUF;
#pragma unroll
        for (int ks = 0; ks < 4; ks++){
            uint32_t a[4][4], b[4][2];
#pragma unroll
            for (int mf = 0; mf < 4; mf++){
                int row = wm*64 + mf*16 + g;
                const uint32_t* p0 = (const uint32_t*)(Ab + row*36 + ks*8);
                const uint32_t* p1 = (const uint32_t*)(Ab + (row+8)*36 + ks*8);
                a[mf][0] = p0[tig];   a[mf][1] = p1[tig];
                a[mf][2] = p0[tig+4]; a[mf][3] = p1[tig+4];
            }
#pragma unroll
            for (int nf = 0; nf < 4; nf++){
                int n = wn*32 + nf*8 + g;
                const uint32_t* p = (const uint32_t*)(Bb + n*36 + ks*8);
                b[nf][0] = p[tig]; b[nf][1] = p[tig+4];
            }
#pragma unroll
            for (int mf = 0; mf < 4; mf++)
#pragma unroll
                for (int nf = 0; nf < 4; nf++)
                    mma_tf32(acc[mf][nf], a[mf], b[nf]);
        }
        buf ^= 1;
    }
}

// =============== QKV GEMM ===============
__global__ __launch_bounds__(256,2) void gemm_qkv(){
    extern __shared__ float sm[];
    int tid = threadIdx.x;
    int c0 = blockIdx.x*128, m0 = blockIdx.y*128;
    float acc[4][4][4] = {};
    tile_gemm(g_xr + (size_t)m0*512, g_wqkvT + (size_t)c0*512, acc, sm, tid);

    const int lane = tid & 31, wid = tid >> 5;
    const int g = lane >> 2, tig = lane & 3;
    const int wm = wid >> 2, wn = wid & 3;
    int sec = c0 >> 9;
    float* dstBase = (sec == 0) ? g_q : (sec == 1 ? g_k : g_v);
    int s0 = (c0 & 511) + wn*32;
    int bb = (m0 >> 11);
#pragma unroll
    for (int mf = 0; mf < 4; mf++){
        int r = m0 + wm*64 + mf*16 + g;
        int n = r & 2047;
#pragma unroll
        for (int nf = 0; nf < 4; nf++){
            int s = s0 + nf*8 + 2*tig;
            int h = s >> 6, d = s & 63;
            float* p = dstBase + ((size_t)((bb*NH + h)*SEQ + n))*HD + d;
            float2 v0 = make_float2(to_tf32(acc[mf][nf][0]), to_tf32(acc[mf][nf][1]));
            float2 v1 = make_float2(to_tf32(acc[mf][nf][2]), to_tf32(acc[mf][nf][3]));
            *reinterpret_cast<float2*>(p) = v0;
            *reinterpret_cast<float2*>(p + 8*HD) = v1;
        }
    }
}

// =============== Out GEMM + bias ===============
__global__ __launch_bounds__(256,2) void gemm_out(const float* __restrict__ bias,
                                                  float* __restrict__ out){
    extern __shared__ float sm[];
    int tid = threadIdx.x;
    int c0 = blockIdx.x*128, m0 = blockIdx.y*128;
    float acc[4][4][4] = {};
    tile_gemm(g_o + (size_t)m0*512, g_woutT + (size_t)c0*512, acc, sm, tid);

    const int lane = tid & 31, wid = tid >> 5;
    const int g = lane >> 2, tig = lane & 3;
    const int wm = wid >> 2, wn = wid & 3;
#pragma unroll
    for (int mf = 0; mf < 4; mf++){
        int r = m0 + wm*64 + mf*16 + g;
#pragma unroll
        for (int nf = 0; nf < 4; nf++){
            int c = c0 + wn*32 + nf*8 + 2*tig;
            float2 bv = *reinterpret_cast<const float2*>(bias + c);
            float2 v0 = make_float2(acc[mf][nf][0] + bv.x, acc[mf][nf][1] + bv.y);
            float2 v1 = make_float2(acc[mf][nf][2] + bv.x, acc[mf][nf][3] + bv.y);
            *reinterpret_cast<float2*>(out + (size_t)r*DIM + c) = v0;
            *reinterpret_cast<float2*>(out + (size_t)(r+8)*DIM + c) = v1;
        }
    }
}

// =============== Flash attention (256 thr, KV tile 64, 2 CTAs/SM) ===============
// smem floats: Q[128*68]=8704, K[64*68]=4352, V[64*68]=4352, P[128*68]=8704, l[128]
#define FQ 0
#define FK 8704
#define FV 13056
#define FP 17408
#define FL 26112
#define FLASH_SMEM (26240*4)   // 104960 B -> 2 CTAs/SM

__global__ __launch_bounds__(256,2) void flash_tc(){
    extern __shared__ float sm[];
    const int tid = threadIdx.x;
    const int lane = tid & 31, wid = tid >> 5;
    const int g = lane >> 2, tig = lane & 3;
    const int wm = wid >> 1, wn = wid & 1;   // 4 q-blocks x 2 col-blocks
    const int q0 = blockIdx.x*128, h = blockIdx.y, b = blockIdx.z;

    const float* Qg = g_q + ((size_t)(b*NH+h)*SEQ + q0)*HD;
    const float* Kg = g_k + (size_t)(b*NH+h)*SEQ*HD;
    const float* Vg = g_v + (size_t)(b*NH+h)*SEQ*HD;

    float* Qs = sm + FQ;
    float* Ks = sm + FK;
    float* Vs = sm + FV;
    float* Ps = sm + FP;
    float* l_sm = sm + FL;
    uint32_t sb = smem_u32(sm);

    if (tid < 128) l_sm[tid] = 0.f;

    // prologue: Q (128 rows), K0, V0 (64 rows each)
    {
        const int f = tid & 15, r0 = tid >> 4;  // f: float4 idx 0..15, r0: 0..15
#pragma unroll
        for (int i = 0; i < 8; i++){
            int r = r0 + i*16;
            CP16(sb + (FQ + r*68 + f*4)*4, Qg + (size_t)r*HD + f*4);
        }
#pragma unroll
        for (int i = 0; i < 4; i++){
            int r = r0 + i*16;
            CP16(sb + (FK + r*68 + f*4)*4, Kg + (size_t)r*HD + f*4);
            CP16(sb + (FV + r*68 + f*4)*4, Vg + (size_t)r*HD + f*4);
        }
        CP_COMMIT();
    }

    float oacc[2][4][4] = {};

    for (int t = 0; t < 32; t++){
        CP_WAIT0();
        __syncthreads();

        // ---- S = Q @ K^T : 128x64, k=64; warp tile 32x32 ----
        float sacc[2][4][4] = {};
#pragma unroll
        for (int ks = 0; ks < 8; ks++){
            uint32_t a[2][4], bq[4][2];
#pragma unroll
            for (int mf = 0; mf < 2; mf++){
                int row = wm*32 + mf*16 + g;
                const uint32_t* p0 = (const uint32_t*)(Qs + row*68 + ks*8);
                const uint32_t* p1 = (const uint32_t*)(Qs + (row+8)*68 + ks*8);
                a[mf][0] = p0[tig];   a[mf][1] = p1[tig];
                a[mf][2] = p0[tig+4]; a[mf][3] = p1[tig+4];
            }
#pragma unroll
            for (int nf = 0; nf < 4; nf++){
                int n = wn*32 + nf*8 + g;
                const uint32_t* p = (const uint32_t*)(Ks + n*68 + ks*8);
                bq[nf][0] = p[tig]; bq[nf][1] = p[tig+4];
            }
#pragma unroll
            for (int mf = 0; mf < 2; mf++)
#pragma unroll
                for (int nf = 0; nf < 4; nf++)
                    mma_tf32(sacc[mf][nf], a[mf], bq[nf]);
        }

        // ---- softmax (no max subtraction), write P ----
#pragma unroll
        for (int mf = 0; mf < 2; mf++){
            int row = wm*32 + mf*16 + g;
            float s0 = 0.f, s1 = 0.f;
#pragma unroll
            for (int nf = 0; nf < 4; nf++){
                float p0 = to_tf32(ex2f(sacc[mf][nf][0]*EXP_C));
                float p1 = to_tf32(ex2f(sacc[mf][nf][1]*EXP_C));
                float p2 = to_tf32(ex2f(sacc[mf][nf][2]*EXP_C));
                float p3 = to_tf32(ex2f(sacc[mf][nf][3]*EXP_C));
                s0 += p0 + p1; s1 += p2 + p3;
                int col = wn*32 + nf*8 + 2*tig;
                *reinterpret_cast<float2*>(Ps + row*68 + col)     = make_float2(p0, p1);
                *reinterpret_cast<float2*>(Ps + (row+8)*68 + col) = make_float2(p2, p3);
            }
            s0 += __shfl_xor_sync(0xffffffffu, s0, 1);
            s0 += __shfl_xor_sync(0xffffffffu, s0, 2);
            s1 += __shfl_xor_sync(0xffffffffu, s1, 1);
            s1 += __shfl_xor_sync(0xffffffffu, s1, 2);
            if (tig == 0){
                atomicAdd(l_sm + row, s0);
                atomicAdd(l_sm + row + 8, s1);
            }
        }
        __syncthreads();   // P ready; K free

        // prefetch next K (K buffer now free)
        if (t < 31){
            const int f = tid & 15, r0 = tid >> 4;
            const float* Kn = Kg + (size_t)(t+1)*64*HD;
#pragma unroll
            for (int i = 0; i < 4; i++){
                int r = r0 + i*16;
                CP16(sb + (FK + r*68 + f*4)*4, Kn + (size_t)r*HD + f*4);
            }
            CP_COMMIT();
        }

        // ---- O += P @ V : 128x64, k=64; warp tile 32x32 ----
#pragma unroll
        for (int ks = 0; ks < 8; ks++){
            uint32_t a[2][4], bv[4][2];
#pragma unroll
            for (int mf = 0; mf < 2; mf++){
                int row = wm*32 + mf*16 + g;
                const uint32_t* p0 = (const uint32_t*)(Ps + row*68 + ks*8);
                const uint32_t* p1 = (const uint32_t*)(Ps + (row+8)*68 + ks*8);
                a[mf][0] = p0[tig];   a[mf][1] = p1[tig];
                a[mf][2] = p0[tig+4]; a[mf][3] = p1[tig+4];
            }
#pragma unroll
            for (int nf = 0; nf < 4; nf++){
                int c = wn*32 + nf*8 + g;
                bv[nf][0] = *(const uint32_t*)(Vs + (ks*8 + tig)*68 + c);
                bv[nf][1] = *(const uint32_t*)(Vs + (ks*8 + tig + 4)*68 + c);
            }
#pragma unroll
            for (int mf = 0; mf < 2; mf++)
#pragma unroll
                for (int nf = 0; nf < 4; nf++)
                    mma_tf32(oacc[mf][nf], a[mf], bv[nf]);
        }
        __syncthreads();   // V free; P free

        // prefetch next V (V buffer now free)
        if (t < 31){
            const int f = tid & 15, r0 = tid >> 4;
            const float* Vn = Vg + (size_t)(t+1)*64*HD;
#pragma unroll
            for (int i = 0; i < 4; i++){
                int r = r0 + i*16;
                CP16(sb + (FV + r*68 + f*4)*4, Vn + (size_t)r*HD + f*4);
            }
            CP_COMMIT();
        }
    }

    // epilogue: normalize, round, write [b,n,h*64+d]
#pragma unroll
    for (int mf = 0; mf < 2; mf++){
        int row = wm*32 + mf*16 + g;
        float inv0 = 1.f / l_sm[row];
        float inv1 = 1.f / l_sm[row + 8];
        int n = q0 + row;
        float* base0 = g_o + ((size_t)(b*SEQ + n))*INNER + h*HD;
        float* base1 = base0 + (size_t)8*INNER;
#pragma unroll
        for (int nf = 0; nf < 4; nf++){
            int d = wn*32 + nf*8 + 2*tig;
            *reinterpret_cast<float2*>(base0 + d) =
                make_float2(to_tf32(oacc[mf][nf][0]*inv0), to_tf32(oacc[mf][nf][1]*inv0));
            *reinterpret_cast<float2*>(base1 + d) =
                make_float2(to_tf32(oacc[mf][nf][2]*inv1), to_tf32(oacc[mf][nf][3]*inv1));
        }
    }
}

// =============== launch ===============
extern "C" void kernel_launch(void* const* d_in, const int* in_sizes, int n_in,
                              void* d_out, int out_size) {
    const float* x     = (const float*)d_in[0];
    const float* w_qkv = (const float*)d_in[1];
    const float* w_out = (const float*)d_in[2];
    const float* b_out = (const float*)d_in[3];
    float* out = (float*)d_out;

    cudaFuncSetAttribute(gemm_qkv, cudaFuncAttributeMaxDynamicSharedMemorySize, GEMM_SMEM);
    cudaFuncSetAttribute(gemm_out, cudaFuncAttributeMaxDynamicSharedMemorySize, GEMM_SMEM);
    cudaFuncSetAttribute(flash_tc, cudaFuncAttributeMaxDynamicSharedMemorySize, FLASH_SMEM);

    float4* xr4;
    { void* p; cudaGetSymbolAddress(&p, g_xr); xr4 = (float4*)p; }
    float* wqkvT; { void* p; cudaGetSymbolAddress(&p, g_wqkvT); wqkvT = (float*)p; }
    float* woutT; { void* p; cudaGetSymbolAddress(&p, g_woutT); woutT = (float*)p; }

    round_x<<<(MTOT*DIM/4)/512, 512>>>((const float4*)x, xr4);
    transpose_mat<<<dim3(NQKV/32, DIM/32), dim3(32,8)>>>(w_qkv, wqkvT, DIM, NQKV);
    transpose_mat<<<dim3(DIM/32, INNER/32), dim3(32,8)>>>(w_out, woutT, INNER, DIM);

    gemm_qkv<<<dim3(NQKV/128, MTOT/128), 256, GEMM_SMEM>>>();
    flash_tc<<<dim3(SEQ/128, NH, BATCH), 256, FLASH_SMEM>>>();
    gemm_out<<<dim3(DIM/128, MTOT/128), 256, GEMM_SMEM>>>(b_out, out);
}

// round 6
// speedup vs baseline: 1.7819x; 1.0350x over previous
#include <cuda_runtime.h>
#include <cstdint>
#include <math.h>

#define BATCH 4
#define SEQ 2048
#define DIM 512
#define NH 8
#define HD 64
#define INNER 512
#define MTOT (BATCH*SEQ)
#define NQKV (3*INNER)
#define EXP_C 0.18033688f   // 0.125 * log2(e)

// ---- scratch (__device__ globals; alloc-free rule) ----
// g_q: permuted per (b,h,qtile): 2 chunks x 4096 floats
// g_k, g_v: row-major [b,h,n,d]
// g_o, g_xr: permuted per m-tile: 16 chunks x 4096 floats
__device__ float g_q[(size_t)BATCH*NH*SEQ*HD];
__device__ float g_k[(size_t)BATCH*NH*SEQ*HD];
__device__ float g_v[(size_t)BATCH*NH*SEQ*HD];
__device__ float g_o[(size_t)MTOT*INNER];
__device__ float g_xr[(size_t)MTOT*DIM];
__device__ float g_wqkvT[(size_t)NQKV*DIM];
__device__ float g_woutT[(size_t)DIM*INNER];

// =============== helpers ===============
__device__ __forceinline__ uint32_t smem_u32(const void* p){
    uint32_t a;
    asm("{ .reg .u64 t; cvta.to.shared.u64 t, %1; cvt.u32.u64 %0, t; }":"=r"(a):"l"(p));
    return a;
}
__device__ __forceinline__ float to_tf32(float x){
    uint32_t r; asm("cvt.rna.tf32.f32 %0, %1;" : "=r"(r) : "f"(x));
    return __uint_as_float(r);
}
__device__ __forceinline__ float ex2f(float x){
    float r; asm("ex2.approx.f32 %0, %1;" : "=f"(r) : "f"(x)); return r;
}
#define CP16(dst,src) asm volatile("cp.async.cg.shared.global [%0], [%1], 16;" :: "r"(dst), "l"(src) : "memory")
#define CP_COMMIT()   asm volatile("cp.async.commit_group;" ::: "memory")
#define CP_WAIT0()    asm volatile("cp.async.wait_group 0;" ::: "memory")

__device__ __forceinline__ void mma_tf32(float c[4], const uint32_t a[4], const uint32_t b[2]){
    asm volatile("mma.sync.aligned.m16n8k8.row.col.f32.tf32.tf32.f32 "
        "{%0,%1,%2,%3},{%4,%5,%6,%7},{%8,%9},{%0,%1,%2,%3};"
        : "+f"(c[0]),"+f"(c[1]),"+f"(c[2]),"+f"(c[3])
        : "r"(a[0]),"r"(a[1]),"r"(a[2]),"r"(a[3]),"r"(b[0]),"r"(b[1]));
}
// load A fragment: one LDS.128 from permuted layout
__device__ __forceinline__ void ldA(uint32_t a[4], const float* chunkBase, int m16, int ks, int lane){
    const float4 v = reinterpret_cast<const float4*>(chunkBase)[(m16*4+ks)*32 + lane];
    a[0]=__float_as_uint(v.x); a[1]=__float_as_uint(v.y);
    a[2]=__float_as_uint(v.z); a[3]=__float_as_uint(v.w);
}

// =============== pre-pass: permute+round x ===============
__global__ void round_x_perm(const float* __restrict__ x, float* __restrict__ xr){
    __shared__ float t[128*33];
    const int mt = blockIdx.y, ch = blockIdx.x;
    const int tid = threadIdx.x;
#pragma unroll
    for (int i = 0; i < 4; i++){
        int v = tid + i*256;
        int r = v >> 3, f = v & 7;
        float4 val = *reinterpret_cast<const float4*>(x + (size_t)(mt*128 + r)*DIM + ch*32 + f*4);
        t[r*33 + f*4+0] = val.x; t[r*33 + f*4+1] = val.y;
        t[r*33 + f*4+2] = val.z; t[r*33 + f*4+3] = val.w;
    }
    __syncthreads();
    float* dst = xr + ((size_t)mt*16 + ch)*4096;
#pragma unroll
    for (int i = 0; i < 4; i++){
        int p = tid + i*256;
        int lane = p & 31, ks = (p>>5)&3, m16 = p>>7;
        int g = lane>>2, tg = lane&3;
        float4 o;
        o.x = to_tf32(t[(m16*16+g  )*33 + ks*8+tg  ]);
        o.y = to_tf32(t[(m16*16+g+8)*33 + ks*8+tg  ]);
        o.z = to_tf32(t[(m16*16+g  )*33 + ks*8+tg+4]);
        o.w = to_tf32(t[(m16*16+g+8)*33 + ks*8+tg+4]);
        reinterpret_cast<float4*>(dst)[p] = o;
    }
}

__global__ void transpose_mat(const float* __restrict__ src, float* __restrict__ dst,
                              int R, int C){
    __shared__ float t[32][33];
    int bx = blockIdx.x * 32, by = blockIdx.y * 32;
    int tx = threadIdx.x;
    for (int yy = threadIdx.y; yy < 32; yy += 8)
        t[yy][tx] = src[(size_t)(by+yy)*C + bx + tx];
    __syncthreads();
    for (int yy = threadIdx.y; yy < 32; yy += 8)
        dst[(size_t)(bx+yy)*R + by + tx] = to_tf32(t[tx][yy]);
}

// =============== shared GEMM mainloop ===============
#define GEMM_ABUF 4096
#define GEMM_BBUF 4608
#define GEMM_SMEM ((2*GEMM_ABUF + 2*GEMM_BBUF)*4)   // 69632 B

__device__ __forceinline__ void tile_gemm(const float* __restrict__ Ag,
                                          const float* __restrict__ Bg,
                                          float acc[4][4][4], float* sm, int tid){
    const int f = tid & 7, r0 = tid >> 3;
    const int lane = tid & 31, wid = tid >> 5;
    const int g = lane >> 2, tig = lane & 3;
    const int wm = wid >> 2, wn = wid & 3;
    float* As = sm;
    float* Bs = sm + 2*GEMM_ABUF;
    uint32_t asb = smem_u32(As), bsb = smem_u32(Bs);

#pragma unroll
    for (int i = 0; i < 4; i++)
        CP16(asb + (tid*4 + i*1024)*4, Ag + tid*4 + i*1024);
#pragma unroll
    for (int i = 0; i < 4; i++){
        int r = r0 + i*32;
        CP16(bsb + (r*36 + f*4)*4, Bg + (size_t)r*512 + f*4);
    }
    CP_COMMIT();

    int buf = 0;
    for (int kc = 0; kc < 16; kc++){
        CP_WAIT0();
        __syncthreads();
        if (kc < 15){
            int k0 = (kc+1)*32, nb = buf ^ 1;
#pragma unroll
            for (int i = 0; i < 4; i++)
                CP16(asb + (nb*GEMM_ABUF + tid*4 + i*1024)*4, Ag + (kc+1)*4096 + tid*4 + i*1024);
#pragma unroll
            for (int i = 0; i < 4; i++){
                int r = r0 + i*32;
                CP16(bsb + (nb*GEMM_BBUF + r*36 + f*4)*4, Bg + (size_t)r*512 + k0 + f*4);
            }
            CP_COMMIT();
        }
        const float* Ab = As + buf*GEMM_ABUF;
        const float* Bb = Bs + buf*GEMM_BBUF;
#pragma unroll
        for (int ks = 0; ks < 4; ks++){
            uint32_t a[4][4], b[4][2];
#pragma unroll
            for (int mf = 0; mf < 4; mf++)
                ldA(a[mf], Ab, wm*4+mf, ks, lane);
#pragma unroll
            for (int nf = 0; nf < 4; nf++){
                int n = wn*32 + nf*8 + g;
                const uint32_t* p = (const uint32_t*)(Bb + n*36 + ks*8);
                b[nf][0] = p[tig]; b[nf][1] = p[tig+4];
            }
#pragma unroll
            for (int mf = 0; mf < 4; mf++)
#pragma unroll
                for (int nf = 0; nf < 4; nf++)
                    mma_tf32(acc[mf][nf], a[mf], b[nf]);
        }
        buf ^= 1;
    }
}

// =============== QKV GEMM ===============
__global__ __launch_bounds__(256,2) void gemm_qkv(){
    extern __shared__ float sm[];
    int tid = threadIdx.x;
    int c0 = blockIdx.x*128, m0 = blockIdx.y*128;
    float acc[4][4][4] = {};
    tile_gemm(g_xr + (size_t)(m0>>7)*65536, g_wqkvT + (size_t)c0*512, acc, sm, tid);

    const int lane = tid & 31, wid = tid >> 5;
    const int g = lane >> 2, tig = lane & 3;
    const int wm = wid >> 2, wn = wid & 3;
    int sec = c0 >> 9;
    int s0 = (c0 & 511) + wn*32;
    int bb = (m0 >> 11);
    if (sec == 0){
        int qt = (m0 & 2047) >> 7;
#pragma unroll
        for (int mf = 0; mf < 4; mf++){
            int m16 = wm*4 + mf;
#pragma unroll
            for (int nf = 0; nf < 4; nf++){
#pragma unroll
                for (int e = 0; e < 4; e++){
                    int dc = e & 1, dr8 = e >> 1;
                    int s = s0 + nf*8 + 2*tig + dc;
                    int h = s >> 6, d = s & 63;
                    int ch = d >> 5, kk = d & 31;
                    int ks = kk >> 3, t = kk & 7;
                    int lp = g*4 + (t & 3);
                    int j = dr8 + 2*(t >> 2);
                    g_q[((size_t)(bb*NH + h)*16 + qt)*8192 + ch*4096
                        + ((m16*4 + ks)*32 + lp)*4 + j] = to_tf32(acc[mf][nf][dr8*2 + dc]);
                }
            }
        }
    } else {
        float* dstBase = (sec == 1) ? g_k : g_v;
#pragma unroll
        for (int mf = 0; mf < 4; mf++){
            int r = m0 + wm*64 + mf*16 + g;
            int n = r & 2047;
#pragma unroll
            for (int nf = 0; nf < 4; nf++){
                int s = s0 + nf*8 + 2*tig;
                int h = s >> 6, d = s & 63;
                float* p = dstBase + ((size_t)((bb*NH + h)*SEQ + n))*HD + d;
                float2 v0 = make_float2(to_tf32(acc[mf][nf][0]), to_tf32(acc[mf][nf][1]));
                float2 v1 = make_float2(to_tf32(acc[mf][nf][2]), to_tf32(acc[mf][nf][3]));
                *reinterpret_cast<float2*>(p) = v0;
                *reinterpret_cast<float2*>(p + 8*HD) = v1;
            }
        }
    }
}

// =============== Out GEMM + bias ===============
__global__ __launch_bounds__(256,2) void gemm_out(const float* __restrict__ bias,
                                                  float* __restrict__ out){
    extern __shared__ float sm[];
    int tid = threadIdx.x;
    int c0 = blockIdx.x*128, m0 = blockIdx.y*128;
    float acc[4][4][4] = {};
    tile_gemm(g_o + (size_t)(m0>>7)*65536, g_woutT + (size_t)c0*512, acc, sm, tid);

    const int lane = tid & 31, wid = tid >> 5;
    const int g = lane >> 2, tig = lane & 3;
    const int wm = wid >> 2, wn = wid & 3;
#pragma unroll
    for (int mf = 0; mf < 4; mf++){
        int r = m0 + wm*64 + mf*16 + g;
#pragma unroll
        for (int nf = 0; nf < 4; nf++){
            int c = c0 + wn*32 + nf*8 + 2*tig;
            float2 bv = *reinterpret_cast<const float2*>(bias + c);
            float2 v0 = make_float2(acc[mf][nf][0] + bv.x, acc[mf][nf][1] + bv.y);
            float2 v1 = make_float2(acc[mf][nf][2] + bv.x, acc[mf][nf][3] + bv.y);
            *reinterpret_cast<float2*>(out + (size_t)r*DIM + c) = v0;
            *reinterpret_cast<float2*>(out + (size_t)(r+8)*DIM + c) = v1;
        }
    }
}

// =============== Flash attention ===============
#define FQ 0
#define FK 8192
#define FV 12544
#define FP 16896
#define FL 25600
#define FLASH_SMEM (25728*4)   // 102912 B -> 2 CTAs/SM

__global__ __launch_bounds__(256,2) void flash_tc(){
    extern __shared__ float sm[];
    const int tid = threadIdx.x;
    const int lane = tid & 31, wid = tid >> 5;
    const int g = lane >> 2, tig = lane & 3;
    const int wm = wid >> 1, wn = wid & 1;
    const int q0 = blockIdx.x*128, h = blockIdx.y, b = blockIdx.z;

    const float* Qg = g_q + ((size_t)(b*NH+h)*16 + (q0>>7))*8192;
    const float* Kg = g_k + (size_t)(b*NH+h)*SEQ*HD;
    const float* Vg = g_v + (size_t)(b*NH+h)*SEQ*HD;

    float* Qs = sm + FQ;
    float* Ks = sm + FK;
    float* Vs = sm + FV;
    float* Ps = sm + FP;
    float* l_sm = sm + FL;
    uint32_t sb = smem_u32(sm);

    if (tid < 128) l_sm[tid] = 0.f;

    {
#pragma unroll
        for (int i = 0; i < 8; i++)
            CP16(sb + (FQ + tid*4 + i*1024)*4, Qg + tid*4 + i*1024);
        const int f = tid & 15, r0 = tid >> 4;
#pragma unroll
        for (int i = 0; i < 4; i++){
            int r = r0 + i*16;
            CP16(sb + (FK + r*68 + f*4)*4, Kg + (size_t)r*HD + f*4);
            CP16(sb + (FV + r*68 + f*4)*4, Vg + (size_t)r*HD + f*4);
        }
        CP_COMMIT();
    }

    float oacc[2][4][4] = {};

    for (int t = 0; t < 32; t++){
        CP_WAIT0();
        __syncthreads();

        // ---- S = Q @ K^T ----
        float sacc[2][4][4] = {};
#pragma unroll
        for (int ks = 0; ks < 8; ks++){
            uint32_t a[2][4], bq[4][2];
            const float* Qc = Qs + (ks>>2)*4096;
#pragma unroll
            for (int mf = 0; mf < 2; mf++)
                ldA(a[mf], Qc, wm*2+mf, ks&3, lane);
#pragma unroll
            for (int nf = 0; nf < 4; nf++){
                int n = wn*32 + nf*8 + g;
                const uint32_t* p = (const uint32_t*)(Ks + n*68 + ks*8);
                bq[nf][0] = p[tig]; bq[nf][1] = p[tig+4];
            }
#pragma unroll
            for (int mf = 0; mf < 2; mf++)
#pragma unroll
                for (int nf = 0; nf < 4; nf++)
                    mma_tf32(sacc[mf][nf], a[mf], bq[nf]);
        }

        // ---- softmax ----
#pragma unroll
        for (int mf = 0; mf < 2; mf++){
            int row = wm*32 + mf*16 + g;
            float s0 = 0.f, s1 = 0.f;
#pragma unroll
            for (int nf = 0; nf < 4; nf++){
                float p0 = to_tf32(ex2f(sacc[mf][nf][0]*EXP_C));
                float p1 = to_tf32(ex2f(sacc[mf][nf][1]*EXP_C));
                float p2 = to_tf32(ex2f(sacc[mf][nf][2]*EXP_C));
                float p3 = to_tf32(ex2f(sacc[mf][nf][3]*EXP_C));
                s0 += p0 + p1; s1 += p2 + p3;
                int col = wn*32 + nf*8 + 2*tig;
                *reinterpret_cast<float2*>(Ps + row*68 + col)     = make_float2(p0, p1);
                *reinterpret_cast<float2*>(Ps + (row+8)*68 + col) = make_float2(p2, p3);
            }
            s0 += __shfl_xor_sync(0xffffffffu, s0, 1);
            s0 += __shfl_xor_sync(0xffffffffu, s0, 2);
            s1 += __shfl_xor_sync(0xffffffffu, s1, 1);
            s1 += __shfl_xor_sync(0xffffffffu, s1, 2);
            if (tig == 0){
                atomicAdd(l_sm + row, s0);
                atomicAdd(l_sm + row + 8, s1);
            }
        }
        __syncthreads();

        if (t < 31){
            const int f = tid & 15, r0 = tid >> 4;
            const float* Kn = Kg + (size_t)(t+1)*64*HD;
#pragma unroll
            for (int i = 0; i < 4; i++){
                int r = r0 + i*16;
                CP16(sb + (FK + r*68 + f*4)*4, Kn + (size_t)r*HD + f*4);
            }
            CP_COMMIT();
        }

        // ---- O += P @ V ----
#pragma unroll
        for (int ks = 0; ks < 8; ks++){
            uint32_t a[2][4], bv[4][2];
#pragma unroll
            for (int mf = 0; mf < 2; mf++){
                int row = wm*32 + mf*16 + g;
                const uint32_t* p0 = (const uint32_t*)(Ps + row*68 + ks*8);
                const uint32_t* p1 = (const uint32_t*)(Ps + (row+8)*68 + ks*8);
                a[mf][0] = p0[tig];   a[mf][1] = p1[tig];
                a[mf][2] = p0[tig+4]; a[mf][3] = p1[tig+4];
            }
#pragma unroll
            for (int nf = 0; nf < 4; nf++){
                int c = wn*32 + nf*8 + g;
                bv[nf][0] = *(const uint32_t*)(Vs + (ks*8 + tig)*68 + c);
                bv[nf][1] = *(const uint32_t*)(Vs + (ks*8 + tig + 4)*68 + c);
            }
#pragma unroll
            for (int mf = 0; mf < 2; mf++)
#pragma unroll
                for (int nf = 0; nf < 4; nf++)
                    mma_tf32(oacc[mf][nf], a[mf], bv[nf]);
        }
        __syncthreads();

        if (t < 31){
            const int f = tid & 15, r0 = tid >> 4;
            const float* Vn = Vg + (size_t)(t+1)*64*HD;
#pragma unroll
            for (int i = 0; i < 4; i++){
                int r = r0 + i*16;
                CP16(sb + (FV + r*68 + f*4)*4, Vn + (size_t)r*HD + f*4);
            }
            CP_COMMIT();
        }
    }

    // epilogue: normalize, permuted write into g_o
    {
        size_t mt = (size_t)(b*16) + (q0>>7);
        float* obase = g_o + mt*65536 + (size_t)(2*h + wn)*4096;
#pragma unroll
        for (int mf = 0; mf < 2; mf++){
            int row = wm*32 + mf*16 + g;
            float inv0 = 1.f / l_sm[row];
            float inv1 = 1.f / l_sm[row + 8];
            int m16 = wm*2 + mf;
#pragma unroll
            for (int nf = 0; nf < 4; nf++){
#pragma unroll
                for (int e = 0; e < 4; e++){
                    int dc = e & 1, dr8 = e >> 1;
                    int c2 = 2*tig + dc;
                    int lp = g*4 + (c2 & 3);
                    int j = dr8 + 2*(c2 >> 2);
                    float val = oacc[mf][nf][dr8*2 + dc] * (dr8 ? inv1 : inv0);
                    obase[((m16*4 + nf)*32 + lp)*4 + j] = to_tf32(val);
                }
            }
        }
    }
}

// =============== launch ===============
extern "C" void kernel_launch(void* const* d_in, const int* in_sizes, int n_in,
                              void* d_out, int out_size) {
    const float* x     = (const float*)d_in[0];
    const float* w_qkv = (const float*)d_in[1];
    const float* w_out = (const float*)d_in[2];
    const float* b_out = (const float*)d_in[3];
    float* out = (float*)d_out;

    cudaFuncSetAttribute(gemm_qkv, cudaFuncAttributeMaxDynamicSharedMemorySize, GEMM_SMEM);
    cudaFuncSetAttribute(gemm_out, cudaFuncAttributeMaxDynamicSharedMemorySize, GEMM_SMEM);
    cudaFuncSetAttribute(flash_tc, cudaFuncAttributeMaxDynamicSharedMemorySize, FLASH_SMEM);

    float* xr;    { void* p; cudaGetSymbolAddress(&p, g_xr); xr = (float*)p; }
    float* wqkvT; { void* p; cudaGetSymbolAddress(&p, g_wqkvT); wqkvT = (float*)p; }
    float* woutT; { void* p; cudaGetSymbolAddress(&p, g_woutT); woutT = (float*)p; }

    round_x_perm<<<dim3(16, MTOT/128), 256>>>(x, xr);
    transpose_mat<<<dim3(NQKV/32, DIM/32), dim3(32,8)>>>(w_qkv, wqkvT, DIM, NQKV);
    transpose_mat<<<dim3(DIM/32, INNER/32), dim3(32,8)>>>(w_out, woutT, INNER, DIM);

    gemm_qkv<<<dim3(NQKV/128, MTOT/128), 256, GEMM_SMEM>>>();
    flash_tc<<<dim3(SEQ/128, NH, BATCH), 256, FLASH_SMEM>>>();
    gemm_out<<<dim3(DIM/128, MTOT/128), 256, GEMM_SMEM>>>(b_out, out);
}